// round 7
// baseline (speedup 1.0000x reference)
#include <cuda_runtime.h>
#include <cuda_bf16.h>
#include <cstdint>

#define BB 64
#define TT 1024
#define CC 512
#define HH 256
#define NE 30
#define STEPS 501
#define NG 1024          // gemm output cols: 768 gates + 256 gh_n
#define WROWS 800        // wcat rows: 512 ctx + 30 onehot + 256 hidden + 2 pad

// ---------------- static scratch (no allocation) ----------------
__device__ float d_proj[(size_t)BB * TT * HH];   // 64 MB
__device__ float d_wcat[WROWS * NG];             // 3.3 MB

__device__ __forceinline__ float tanha(float x) {
    float y; asm("tanh.approx.f32 %0, %1;" : "=f"(y) : "f"(x)); return y;
}

// ---------------- setup: build concatenated GRU weight ----------------
// rows 0..511: w_ih context rows; 512..541: w_ih onehot rows; 542..797: w_hh; 798..799 pad
// cols 0..767: the 3 gates (x+h combined); cols 768..1023: w_hh n-gate alone
__global__ void k_setup(const float* __restrict__ w_ih, const float* __restrict__ w_hh) {
    int idx = blockIdx.x * 256 + threadIdx.x;
    if (idx >= WROWS * NG) return;
    int k = idx >> 10, j = idx & 1023;
    float v = 0.f;
    if (j < 768) {
        if (k < 542)      v = w_ih[k * 768 + j];
        else if (k < 798) v = w_hh[(k - 542) * 768 + j];
    } else {
        if (k >= 542 && k < 798) v = w_hh[(k - 542) * 768 + 512 + (j - 768)];
    }
    d_wcat[idx] = v;
}

// ---------------- proj[b,t,h] = sum_c fea[b,c,t] * i2h_w[c,h] ----------------
__global__ __launch_bounds__(256) void k_proj(const float* __restrict__ fea,
                                              const float* __restrict__ i2h_w) {
    int t0 = blockIdx.x * 64, h0 = blockIdx.y * 64, b = blockIdx.z;
    __shared__ float As[8][64];
    __shared__ float Bs[8][64];
    int tid = threadIdx.x;
    int tx = tid & 15, ty = tid >> 4;
    float acc[4][4] = {};
    for (int k0 = 0; k0 < CC; k0 += 8) {
        #pragma unroll
        for (int r = 0; r < 2; r++) {
            int i = tid + r * 256;
            int kk = i >> 6, m = i & 63;
            As[kk][m] = fea[((size_t)b * CC + (k0 + kk)) * TT + t0 + m];
            Bs[kk][m] = i2h_w[(k0 + kk) * HH + h0 + m];
        }
        __syncthreads();
        #pragma unroll
        for (int kk = 0; kk < 8; kk++) {
            float a[4], bv[4];
            #pragma unroll
            for (int i = 0; i < 4; i++) a[i] = As[kk][ty * 4 + i];
            #pragma unroll
            for (int j = 0; j < 4; j++) bv[j] = Bs[kk][tx * 4 + j];
            #pragma unroll
            for (int i = 0; i < 4; i++)
                #pragma unroll
                for (int j = 0; j < 4; j++) acc[i][j] += a[i] * bv[j];
        }
        __syncthreads();
    }
    #pragma unroll
    for (int i = 0; i < 4; i++) {
        float4 v = make_float4(acc[i][0], acc[i][1], acc[i][2], acc[i][3]);
        *(float4*)&d_proj[((size_t)b * TT + t0 + ty * 4 + i) * HH + h0 + tx * 4] = v;
    }
}

// ---------------- persistent decode: one CTA per batch, 501 steps ----------------
__global__ __launch_bounds__(1024, 1) void k_decode(
    const float* __restrict__ fea, const int* __restrict__ targets,
    const float* __restrict__ score_w,
    const float* __restrict__ b_ih, const float* __restrict__ b_hh,
    const float* __restrict__ sg1_w, const float* __restrict__ sg1_b,
    const float* __restrict__ sg2_w, const float* __restrict__ sg2_b,
    const float* __restrict__ lg1_w, const float* __restrict__ lg1_b,
    const float* __restrict__ lg2_w, const float* __restrict__ lg2_b,
    const float* __restrict__ h2h_w, const float* __restrict__ h2h_b,
    float* __restrict__ out)
{
    __shared__ __align__(16) float s_alpha[TT];   // e -> alpha
    __shared__ __align__(16) float s_ctx[CC];
    __shared__ __align__(16) float s_hid[HH];
    __shared__ __align__(16) float s_ph[HH];
    __shared__ __align__(16) float s_g[NG];
    __shared__ __align__(16) float s_scr[4096];   // gemm / head partials (reused)
    __shared__ float s_s1[HH], s_l1[HH];
    __shared__ float s_red[32];

    int b = blockIdx.x;
    int tid = threadIdx.x, wid = tid >> 5, lane = tid & 31;

    if (tid < HH) { s_hid[tid] = 0.f; s_ph[tid] = h2h_b[tid]; }   // h0=0 -> ph=bias
    float rsw[8];
    #pragma unroll
    for (int i = 0; i < 8; i++) rsw[i] = score_w[lane * 8 + i];
    __syncthreads();

    for (int s = 0; s < STEPS; s++) {
        int ch = targets[b * STEPS + s];
        float rph[8];
        #pragma unroll
        for (int i = 0; i < 8; i++) rph[i] = s_ph[lane * 8 + i];

        // ---- scores: warp wid covers t = wid*32 .. +31 ----
        const float4* pbase =
            (const float4*)&d_proj[((size_t)b * TT + wid * 32) * HH + lane * 8];
        #pragma unroll 2
        for (int tt = 0; tt < 32; tt++) {
            const float4* p = pbase + (size_t)tt * (HH / 4);
            float4 p0 = p[0], p1 = p[1];
            float a = tanha(p0.x + rph[0]) * rsw[0] + tanha(p0.y + rph[1]) * rsw[1]
                    + tanha(p0.z + rph[2]) * rsw[2] + tanha(p0.w + rph[3]) * rsw[3]
                    + tanha(p1.x + rph[4]) * rsw[4] + tanha(p1.y + rph[5]) * rsw[5]
                    + tanha(p1.z + rph[6]) * rsw[6] + tanha(p1.w + rph[7]) * rsw[7];
            #pragma unroll
            for (int o = 16; o; o >>= 1) a += __shfl_xor_sync(~0u, a, o);
            if (lane == 0) s_alpha[wid * 32 + tt] = a;
        }
        __syncthreads();

        // ---- softmax over 1024 t (one element per thread) ----
        float e = s_alpha[tid];
        float m = e;
        #pragma unroll
        for (int o = 16; o; o >>= 1) m = fmaxf(m, __shfl_xor_sync(~0u, m, o));
        if (lane == 0) s_red[wid] = m;
        __syncthreads();
        m = s_red[0];
        #pragma unroll
        for (int i = 1; i < 32; i++) m = fmaxf(m, s_red[i]);
        float ex = __expf(e - m);
        float sm = ex;
        #pragma unroll
        for (int o = 16; o; o >>= 1) sm += __shfl_xor_sync(~0u, sm, o);
        __syncthreads();                 // all reads of s_red (max) done
        if (lane == 0) s_red[wid] = sm;
        __syncthreads();
        sm = 0.f;
        #pragma unroll
        for (int i = 0; i < 32; i++) sm += s_red[i];
        s_alpha[tid] = ex * (1.f / sm);
        __syncthreads();

        // ---- context[c] = sum_t alpha[t] * fea[b,c,t] ----
        const float4* al4 = (const float4*)s_alpha;
        #pragma unroll 1
        for (int cc = 0; cc < 16; cc++) {
            int c = wid * 16 + cc;
            const float4* f = (const float4*)&fea[((size_t)b * CC + c) * TT];
            float acc = 0.f;
            #pragma unroll
            for (int q = 0; q < 8; q++) {
                float4 fv = f[lane + 32 * q];
                float4 av = al4[lane + 32 * q];
                acc += fv.x * av.x + fv.y * av.y + fv.z * av.z + fv.w * av.w;
            }
            #pragma unroll
            for (int o = 16; o; o >>= 1) acc += __shfl_xor_sync(~0u, acc, o);
            if (lane == 0) s_ctx[c] = acc;
        }
        __syncthreads();

        // ---- GRU gemm partials: g[n] = sum_k u[k]*Wcat[k,n], k-split x4 ----
        {
            int kq = tid >> 8, ng = tid & 255, n = ng * 4;
            float4 acc = {0.f, 0.f, 0.f, 0.f};
            int k0 = kq * 192;
            #pragma unroll 4
            for (int k = k0; k < k0 + 192; k++) {
                int row  = (k < 512) ? k : k + 30;          // skip onehot rows
                float uv = (k < 512) ? s_ctx[k] : s_hid[k - 512];
                float4 w = *(const float4*)&d_wcat[(size_t)row * NG + n];
                acc.x += uv * w.x; acc.y += uv * w.y;
                acc.z += uv * w.z; acc.w += uv * w.w;
            }
            *(float4*)&s_scr[kq * 1024 + n] = acc;
        }
        __syncthreads();
        s_g[tid] = s_scr[tid] + s_scr[1024 + tid] + s_scr[2048 + tid] + s_scr[3072 + tid]
                 + d_wcat[(size_t)(512 + ch) * NG + tid];   // onehot = single W row
        __syncthreads();

        // ---- gates (accurate transcendentals; tiny count) ----
        if (tid < HH) {
            int h = tid;
            float gr  = s_g[h]       + b_ih[h]       + b_hh[h];
            float gz  = s_g[256 + h] + b_ih[256 + h] + b_hh[256 + h];
            float ghn = s_g[768 + h] + b_hh[512 + h];
            float gxn = (s_g[512 + h] - s_g[768 + h]) + b_ih[512 + h];
            float r = 1.f / (1.f + expf(-gr));
            float z = 1.f / (1.f + expf(-gz));
            float n = tanhf(gxn + r * ghn);
            s_hid[h] = (1.f - z) * n + z * s_hid[h];
        }
        __syncthreads();

        // ---- head matvecs: s1 = h@sg1, l1 = h@lg1, ph = h@h2h (k-split x4) ----
        if (tid < 768) {
            int mm = tid >> 8, idx = tid & 255, kq = idx >> 6, hg = idx & 63;
            const float* w = (mm == 0) ? sg1_w : (mm == 1) ? lg1_w : h2h_w;
            float4 a = {0.f, 0.f, 0.f, 0.f};
            int k0 = kq * 64;
            #pragma unroll 4
            for (int k = k0; k < k0 + 64; k++) {
                float hv = s_hid[k];
                float4 wv = *(const float4*)&w[k * HH + hg * 4];
                a.x += hv * wv.x; a.y += hv * wv.y;
                a.z += hv * wv.z; a.w += hv * wv.w;
            }
            *(float4*)&s_scr[mm * 1024 + kq * 256 + hg * 4] = a;
        }
        __syncthreads();
        if (tid < 768) {
            int mm = tid >> 8, h = tid & 255;
            float v = s_scr[mm * 1024 + h]       + s_scr[mm * 1024 + 256 + h]
                    + s_scr[mm * 1024 + 512 + h] + s_scr[mm * 1024 + 768 + h];
            if (mm == 0)      s_s1[h] = v + sg1_b[h];
            else if (mm == 1) s_l1[h] = v + lg1_b[h];
            else              s_ph[h] = v + h2h_b[h];   // ph for next step
        }
        __syncthreads();

        // ---- output heads ----
        if (tid < NE) {
            float sv = sg2_b[tid];
            #pragma unroll 8
            for (int k = 0; k < HH; k++) sv += s_s1[k] * sg2_w[k * NE + tid];
            out[((size_t)b * STEPS + s) * NE + tid] = sv;
        } else if (tid >= 32 && tid < 36) {
            int j = tid - 32;
            float lv = lg2_b[j];
            #pragma unroll 8
            for (int k = 0; k < HH; k++) lv += s_l1[k] * lg2_w[k * 4 + j];
            out[(size_t)BB * STEPS * NE + ((size_t)b * STEPS + s) * 4 + j] =
                1.f / (1.f + expf(-lv));
        }
        __syncthreads();
    }
}

// ---------------- launch: 3 graph nodes total ----------------
extern "C" void kernel_launch(void* const* d_in, const int* in_sizes, int n_in,
                              void* d_out, int out_size) {
    const float* fea      = (const float*)d_in[0];
    const int*   targets  = (const int*)  d_in[1];
    const float* i2h_w    = (const float*)d_in[2];
    const float* h2h_w    = (const float*)d_in[3];
    const float* h2h_b    = (const float*)d_in[4];
    const float* score_w  = (const float*)d_in[5];
    const float* gru_w_ih = (const float*)d_in[6];
    const float* gru_w_hh = (const float*)d_in[7];
    const float* gru_b_ih = (const float*)d_in[8];
    const float* gru_b_hh = (const float*)d_in[9];
    const float* sg1_w    = (const float*)d_in[10];
    const float* sg1_b    = (const float*)d_in[11];
    const float* sg2_w    = (const float*)d_in[12];
    const float* sg2_b    = (const float*)d_in[13];
    const float* lg1_w    = (const float*)d_in[14];
    const float* lg1_b    = (const float*)d_in[15];
    const float* lg2_w    = (const float*)d_in[16];
    const float* lg2_b    = (const float*)d_in[17];
    float* out = (float*)d_out;

    k_setup<<<(WROWS * NG + 255) / 256, 256>>>(gru_w_ih, gru_w_hh);
    k_proj<<<dim3(TT / 64, HH / 64, BB), 256>>>(fea, i2h_w);
    k_decode<<<BB, 1024>>>(fea, targets, score_w,
                           gru_b_ih, gru_b_hh,
                           sg1_w, sg1_b, sg2_w, sg2_b,
                           lg1_w, lg1_b, lg2_w, lg2_b,
                           h2h_w, h2h_b, out);
}

// round 9
// speedup vs baseline: 1.7675x; 1.7675x over previous
#include <cuda_runtime.h>
#include <cuda_fp16.h>
#include <cstdint>

#define BB 64
#define TT 1024
#define CC 512
#define HH 256
#define NE 30
#define STEPS 501
#define NG 1024          // gemm output cols: 768 gates + 256 gh_n
#define WROWS 800        // wcat rows: 512 ctx + 30 onehot + 256 hidden + 2 pad

// ---------------- static scratch (no allocation) ----------------
__device__ __align__(16) __half d_proj_h[(size_t)BB * TT * HH];  // 32 MB
__device__ __align__(16) __half d_fea_h[(size_t)BB * CC * TT];   // 64 MB
__device__ __align__(16) __half d_wcat_h[WROWS * NG];            // 1.6 MB
__device__ __align__(16) __half d_hw_h[3 * HH * HH];             // 384 KB: sg1 | lg1 | h2h

__device__ __forceinline__ float tanha(float x) {
    float y; asm("tanh.approx.f32 %0, %1;" : "=f"(y) : "f"(x)); return y;
}
__device__ __forceinline__ void h8_to_f(uint4 v, float* f) {
    const __half2* p = (const __half2*)&v;
    #pragma unroll
    for (int i = 0; i < 4; i++) { float2 t = __half22float2(p[i]); f[2*i] = t.x; f[2*i+1] = t.y; }
}

// ---------------- setup: build fp16 Wcat + packed head weights ----------------
__global__ void k_setup(const float* __restrict__ w_ih, const float* __restrict__ w_hh,
                        const float* __restrict__ sg1_w, const float* __restrict__ lg1_w,
                        const float* __restrict__ h2h_w) {
    int idx = blockIdx.x * 256 + threadIdx.x;
    if (idx < WROWS * NG) {
        int k = idx >> 10, j = idx & 1023;
        float v = 0.f;
        if (j < 768) {
            if (k < 542)      v = w_ih[k * 768 + j];
            else if (k < 798) v = w_hh[(k - 542) * 768 + j];
        } else {
            if (k >= 542 && k < 798) v = w_hh[(k - 542) * 768 + 512 + (j - 768)];
        }
        d_wcat_h[idx] = __float2half(v);
    }
    int idx2 = idx - WROWS * NG;
    if (idx2 >= 0 && idx2 < 3 * HH * HH) {
        int mm = idx2 >> 16, i = idx2 & 65535;
        const float* w = (mm == 0) ? sg1_w : (mm == 1) ? lg1_w : h2h_w;
        d_hw_h[idx2] = __float2half(w[i]);
    }
}

// ---------------- fea -> fp16 copy ----------------
__global__ __launch_bounds__(256) void k_conv(const float* __restrict__ fea) {
    size_t i = ((size_t)blockIdx.x * 256 + threadIdx.x) * 4;
    if (i >= (size_t)BB * CC * TT) return;
    float4 v = *(const float4*)&fea[i];
    __half2 a = __floats2half2_rn(v.x, v.y), b = __floats2half2_rn(v.z, v.w);
    *(__half2*)&d_fea_h[i] = a;
    *(__half2*)&d_fea_h[i + 2] = b;
}

// ---------------- proj[b,t,h] = sum_c fea[b,c,t] * i2h_w[c,h] (fp32 acc, fp16 out) ----
__global__ __launch_bounds__(256) void k_proj(const float* __restrict__ fea,
                                              const float* __restrict__ i2h_w) {
    int t0 = blockIdx.x * 64, h0 = blockIdx.y * 64, b = blockIdx.z;
    __shared__ float As[8][64];
    __shared__ float Bs[8][64];
    int tid = threadIdx.x;
    int tx = tid & 15, ty = tid >> 4;
    float acc[4][4] = {};
    for (int k0 = 0; k0 < CC; k0 += 8) {
        #pragma unroll
        for (int r = 0; r < 2; r++) {
            int i = tid + r * 256;
            int kk = i >> 6, m = i & 63;
            As[kk][m] = fea[((size_t)b * CC + (k0 + kk)) * TT + t0 + m];
            Bs[kk][m] = i2h_w[(k0 + kk) * HH + h0 + m];
        }
        __syncthreads();
        #pragma unroll
        for (int kk = 0; kk < 8; kk++) {
            float a[4], bv[4];
            #pragma unroll
            for (int i = 0; i < 4; i++) a[i] = As[kk][ty * 4 + i];
            #pragma unroll
            for (int j = 0; j < 4; j++) bv[j] = Bs[kk][tx * 4 + j];
            #pragma unroll
            for (int i = 0; i < 4; i++)
                #pragma unroll
                for (int j = 0; j < 4; j++) acc[i][j] += a[i] * bv[j];
        }
        __syncthreads();
    }
    #pragma unroll
    for (int i = 0; i < 4; i++) {
        size_t base = ((size_t)b * TT + t0 + ty * 4 + i) * HH + h0 + tx * 4;
        *(__half2*)&d_proj_h[base]     = __floats2half2_rn(acc[i][0], acc[i][1]);
        *(__half2*)&d_proj_h[base + 2] = __floats2half2_rn(acc[i][2], acc[i][3]);
    }
}

// ---------------- ncu alignment no-op ----------------
__global__ void k_nop(int x) { if (x == -123456789) d_wcat_h[0] = __float2half(0.f); }

// ---------------- persistent decode: one CTA per batch, 501 steps ----------------
__global__ __launch_bounds__(1024, 1) void k_decode(
    const int* __restrict__ targets,
    const float* __restrict__ score_w,
    const float* __restrict__ b_ih, const float* __restrict__ b_hh,
    const float* __restrict__ sg1_b, const float* __restrict__ sg2_w,
    const float* __restrict__ sg2_b, const float* __restrict__ lg1_b,
    const float* __restrict__ lg2_w, const float* __restrict__ lg2_b,
    const float* __restrict__ h2h_b,
    float* __restrict__ out)
{
    __shared__ __align__(16) float s_alpha[TT];
    __shared__ __align__(16) float s_ctx[CC];
    __shared__ __align__(16) float s_hid[HH];
    __shared__ __align__(16) float s_ph[HH];
    __shared__ __align__(16) float s_g[NG];
    __shared__ __align__(16) float s_scr[8192];   // 32 KB partials (reused)
    __shared__ float s_s1[HH], s_l1[HH];
    __shared__ float s_red[32];

    int b = blockIdx.x;
    int tid = threadIdx.x, wid = tid >> 5, lane = tid & 31;

    if (tid < HH) { s_hid[tid] = 0.f; s_ph[tid] = h2h_b[tid]; }   // h0=0 -> ph=bias
    float rsw[8];
    #pragma unroll
    for (int i = 0; i < 8; i++) rsw[i] = score_w[lane * 8 + i];
    __syncthreads();

    for (int s = 0; s < STEPS; s++) {
        int ch = targets[b * STEPS + s];
        float rph[8];
        #pragma unroll
        for (int i = 0; i < 8; i++) rph[i] = s_ph[lane * 8 + i];

        // ---- scores: warp wid covers t = wid*32 .. +31 ----
        const uint4* pbase = (const uint4*)&d_proj_h[((size_t)b * TT + wid * 32) * HH + lane * 8];
        #pragma unroll 4
        for (int tt = 0; tt < 32; tt++) {
            uint4 pv = pbase[(size_t)tt * (HH / 8)];
            float p[8]; h8_to_f(pv, p);
            float a = tanha(p[0] + rph[0]) * rsw[0] + tanha(p[1] + rph[1]) * rsw[1]
                    + tanha(p[2] + rph[2]) * rsw[2] + tanha(p[3] + rph[3]) * rsw[3]
                    + tanha(p[4] + rph[4]) * rsw[4] + tanha(p[5] + rph[5]) * rsw[5]
                    + tanha(p[6] + rph[6]) * rsw[6] + tanha(p[7] + rph[7]) * rsw[7];
            #pragma unroll
            for (int o = 16; o; o >>= 1) a += __shfl_xor_sync(~0u, a, o);
            if (lane == 0) s_alpha[wid * 32 + tt] = a;
        }
        __syncthreads();

        // ---- softmax over 1024 t ----
        float e = s_alpha[tid];
        float m = e;
        #pragma unroll
        for (int o = 16; o; o >>= 1) m = fmaxf(m, __shfl_xor_sync(~0u, m, o));
        if (lane == 0) s_red[wid] = m;
        __syncthreads();
        m = s_red[0];
        #pragma unroll
        for (int i = 1; i < 32; i++) m = fmaxf(m, s_red[i]);
        float ex = __expf(e - m);
        float sm = ex;
        #pragma unroll
        for (int o = 16; o; o >>= 1) sm += __shfl_xor_sync(~0u, sm, o);
        __syncthreads();
        if (lane == 0) s_red[wid] = sm;
        __syncthreads();
        sm = 0.f;
        #pragma unroll
        for (int i = 0; i < 32; i++) sm += s_red[i];
        s_alpha[tid] = ex * (1.f / sm);
        __syncthreads();

        // ---- context[c] = sum_t alpha[t] * fea[b,c,t] ----
        #pragma unroll 1
        for (int cc = 0; cc < 16; cc++) {
            int c = wid * 16 + cc;
            const __half* f = &d_fea_h[((size_t)b * CC + c) * TT];
            float acc = 0.f;
            #pragma unroll
            for (int q = 0; q < 4; q++) {
                int t = q * 256 + lane * 8;
                uint4 fv = *(const uint4*)&f[t];
                float fw[8]; h8_to_f(fv, fw);
                const float4* av = (const float4*)&s_alpha[t];
                float4 a0 = av[0], a1 = av[1];
                acc += fw[0]*a0.x + fw[1]*a0.y + fw[2]*a0.z + fw[3]*a0.w
                     + fw[4]*a1.x + fw[5]*a1.y + fw[6]*a1.z + fw[7]*a1.w;
            }
            #pragma unroll
            for (int o = 16; o; o >>= 1) acc += __shfl_xor_sync(~0u, acc, o);
            if (lane == 0) s_ctx[c] = acc;
        }
        __syncthreads();

        // ---- GRU gemm: g[n] = sum_k u[k]*Wcat[k,n], k-split x8, 8 cols/thread ----
        {
            int kq = tid >> 7, ng = tid & 127, n = ng * 8;
            float acc[8] = {};
            int k0 = kq * 96;
            #pragma unroll 4
            for (int k = k0; k < k0 + 96; k++) {
                int row  = (k < 512) ? k : k + 30;          // skip onehot rows
                float uv = (k < 512) ? s_ctx[k] : s_hid[k - 512];
                uint4 wv = *(const uint4*)&d_wcat_h[(size_t)row * NG + n];
                float w[8]; h8_to_f(wv, w);
                #pragma unroll
                for (int j = 0; j < 8; j++) acc[j] += uv * w[j];
            }
            *(float4*)&s_scr[kq * 1024 + n]     = make_float4(acc[0], acc[1], acc[2], acc[3]);
            *(float4*)&s_scr[kq * 1024 + n + 4] = make_float4(acc[4], acc[5], acc[6], acc[7]);
        }
        __syncthreads();
        {
            float g = __half2float(d_wcat_h[(size_t)(512 + ch) * NG + tid]);  // onehot row
            #pragma unroll
            for (int kq = 0; kq < 8; kq++) g += s_scr[kq * 1024 + tid];
            s_g[tid] = g;
        }
        __syncthreads();

        // ---- gates ----
        if (tid < HH) {
            int h = tid;
            float gr  = s_g[h]       + b_ih[h]       + b_hh[h];
            float gz  = s_g[256 + h] + b_ih[256 + h] + b_hh[256 + h];
            float ghn = s_g[768 + h] + b_hh[512 + h];
            float gxn = (s_g[512 + h] - s_g[768 + h]) + b_ih[512 + h];
            float r = 1.f / (1.f + expf(-gr));
            float z = 1.f / (1.f + expf(-gz));
            float n = tanhf(gxn + r * ghn);
            s_hid[h] = (1.f - z) * n + z * s_hid[h];
        }
        __syncthreads();

        // ---- head matvecs: s1 = h@sg1, l1 = h@lg1, ph = h@h2h (k-split x8) ----
        if (tid < 768) {
            int mm = tid >> 8, idx = tid & 255, kq = idx >> 5, hg = idx & 31;
            const __half* w = &d_hw_h[mm * HH * HH];
            float a[8] = {};
            int k0 = kq * 32;
            #pragma unroll 4
            for (int k = k0; k < k0 + 32; k++) {
                float hv = s_hid[k];
                uint4 wv = *(const uint4*)&w[k * HH + hg * 8];
                float wf[8]; h8_to_f(wv, wf);
                #pragma unroll
                for (int j = 0; j < 8; j++) a[j] += hv * wf[j];
            }
            *(float4*)&s_scr[mm * 2048 + kq * 256 + hg * 8]     = make_float4(a[0], a[1], a[2], a[3]);
            *(float4*)&s_scr[mm * 2048 + kq * 256 + hg * 8 + 4] = make_float4(a[4], a[5], a[6], a[7]);
        }
        __syncthreads();
        if (tid < 768) {
            int mm = tid >> 8, h = tid & 255;
            float v = 0.f;
            #pragma unroll
            for (int kq = 0; kq < 8; kq++) v += s_scr[mm * 2048 + kq * 256 + h];
            if (mm == 0)      s_s1[h] = v + sg1_b[h];
            else if (mm == 1) s_l1[h] = v + lg1_b[h];
            else              s_ph[h] = v + h2h_b[h];   // ph for next step
        }
        __syncthreads();

        // ---- output heads (fp32 weights: direct output path) ----
        if (tid < NE) {
            float sv = sg2_b[tid];
            #pragma unroll 8
            for (int k = 0; k < HH; k++) sv += s_s1[k] * sg2_w[k * NE + tid];
            out[((size_t)b * STEPS + s) * NE + tid] = sv;
        } else if (tid >= 32 && tid < 36) {
            int j = tid - 32;
            float lv = lg2_b[j];
            #pragma unroll 8
            for (int k = 0; k < HH; k++) lv += s_l1[k] * lg2_w[k * 4 + j];
            out[(size_t)BB * STEPS * NE + ((size_t)b * STEPS + s) * 4 + j] =
                1.f / (1.f + expf(-lv));
        }
        __syncthreads();
    }
}

// ---------------- launch ----------------
extern "C" void kernel_launch(void* const* d_in, const int* in_sizes, int n_in,
                              void* d_out, int out_size) {
    const float* fea      = (const float*)d_in[0];
    const int*   targets  = (const int*)  d_in[1];
    const float* i2h_w    = (const float*)d_in[2];
    const float* h2h_w    = (const float*)d_in[3];
    const float* h2h_b    = (const float*)d_in[4];
    const float* score_w  = (const float*)d_in[5];
    const float* gru_w_ih = (const float*)d_in[6];
    const float* gru_w_hh = (const float*)d_in[7];
    const float* gru_b_ih = (const float*)d_in[8];
    const float* gru_b_hh = (const float*)d_in[9];
    const float* sg1_w    = (const float*)d_in[10];
    const float* sg1_b    = (const float*)d_in[11];
    const float* sg2_w    = (const float*)d_in[12];
    const float* sg2_b    = (const float*)d_in[13];
    const float* lg1_w    = (const float*)d_in[14];
    const float* lg1_b    = (const float*)d_in[15];
    const float* lg2_w    = (const float*)d_in[16];
    const float* lg2_b    = (const float*)d_in[17];
    float* out = (float*)d_out;

    int setup_elems = WROWS * NG + 3 * HH * HH;
    k_setup<<<(setup_elems + 255) / 256, 256>>>(gru_w_ih, gru_w_hh, sg1_w, lg1_w, h2h_w);
    k_conv<<<(int)(((size_t)BB * CC * TT / 4 + 255) / 256), 256>>>(fea);
    k_proj<<<dim3(TT / 64, HH / 64, BB), 256>>>(fea, i2h_w);
    k_nop<<<1, 32>>>(0);
    k_nop<<<1, 32>>>(0);   // decode is launch #5 -> ncu -s 5 -c 1 profiles it
    k_decode<<<BB, 1024>>>(targets, score_w,
                           gru_b_ih, gru_b_hh,
                           sg1_b, sg2_w, sg2_b,
                           lg1_b, lg2_w, lg2_b,
                           h2h_b, out);
}

// round 10
// speedup vs baseline: 2.4810x; 1.4037x over previous
#include <cuda_runtime.h>
#include <cuda_fp16.h>
#include <cstdint>

#define BB 64
#define TT 1024
#define CC 512
#define HH 256
#define NE 30
#define STEPS 501
#define NG 1024          // gemm output cols: 768 gates + 256 gh_n
#define WROWS 800        // wcat rows: 512 ctx + 30 onehot + 256 hidden + 2 pad
#define HT 512           // T half per CTA

// ---------------- static scratch (no allocation) ----------------
__device__ __align__(16) __half d_proj_h[(size_t)BB * TT * HH];  // 32 MB
__device__ __align__(16) __half d_fea_h[(size_t)BB * CC * TT];   // 64 MB
__device__ __align__(16) __half d_wcat_h[WROWS * NG];            // 1.6 MB
__device__ __align__(16) __half d_hw_h[3 * HH * HH];             // sg1 | lg1 | h2h
// cross-CTA exchange (parity double-buffered) + flags
__device__ __align__(16) float d_xv[2][BB][2][516];              // ctx partial + m,S
__device__ __align__(16) float d_xg[2][BB][2][512];              // gemm halves
__device__ int d_flag[BB][2][2];                                 // [b][p][phase]

__device__ __forceinline__ float tanha(float x) {
    float y; asm("tanh.approx.f32 %0, %1;" : "=f"(y) : "f"(x)); return y;
}
__device__ __forceinline__ void h8_to_f(uint4 v, float* f) {
    const __half2* p = (const __half2*)&v;
    #pragma unroll
    for (int i = 0; i < 4; i++) { float2 t = __half22float2(p[i]); f[2*i] = t.x; f[2*i+1] = t.y; }
}
__device__ __forceinline__ void h4_to_f(uint2 v, float* f) {
    const __half2* p = (const __half2*)&v;
    float2 a = __half22float2(p[0]), c = __half22float2(p[1]);
    f[0] = a.x; f[1] = a.y; f[2] = c.x; f[3] = c.y;
}

// ---------------- setup: fp16 Wcat + head weights + flag reset ----------------
__global__ void k_setup(const float* __restrict__ w_ih, const float* __restrict__ w_hh,
                        const float* __restrict__ sg1_w, const float* __restrict__ lg1_w,
                        const float* __restrict__ h2h_w) {
    int idx = blockIdx.x * 256 + threadIdx.x;
    if (idx < BB * 2 * 2) ((int*)d_flag)[idx] = 0;
    if (idx < WROWS * NG) {
        int k = idx >> 10, j = idx & 1023;
        float v = 0.f;
        if (j < 768) {
            if (k < 542)      v = w_ih[k * 768 + j];
            else if (k < 798) v = w_hh[(k - 542) * 768 + j];
        } else {
            if (k >= 542 && k < 798) v = w_hh[(k - 542) * 768 + 512 + (j - 768)];
        }
        d_wcat_h[idx] = __float2half(v);
    }
    int idx2 = idx - WROWS * NG;
    if (idx2 >= 0 && idx2 < 3 * HH * HH) {
        int mm = idx2 >> 16, i = idx2 & 65535;
        const float* w = (mm == 0) ? sg1_w : (mm == 1) ? lg1_w : h2h_w;
        d_hw_h[idx2] = __float2half(w[i]);
    }
}

// ---------------- fea -> fp16 ----------------
__global__ __launch_bounds__(256) void k_conv(const float* __restrict__ fea) {
    size_t i = ((size_t)blockIdx.x * 256 + threadIdx.x) * 4;
    if (i >= (size_t)BB * CC * TT) return;
    float4 v = *(const float4*)&fea[i];
    *(__half2*)&d_fea_h[i]     = __floats2half2_rn(v.x, v.y);
    *(__half2*)&d_fea_h[i + 2] = __floats2half2_rn(v.z, v.w);
}

// ---------------- proj[b,t,h] = sum_c fea[b,c,t] * i2h_w[c,h] ----------------
__global__ __launch_bounds__(256) void k_proj(const float* __restrict__ fea,
                                              const float* __restrict__ i2h_w) {
    int t0 = blockIdx.x * 64, h0 = blockIdx.y * 64, b = blockIdx.z;
    __shared__ float As[8][64];
    __shared__ float Bs[8][64];
    int tid = threadIdx.x;
    int tx = tid & 15, ty = tid >> 4;
    float acc[4][4] = {};
    for (int k0 = 0; k0 < CC; k0 += 8) {
        #pragma unroll
        for (int r = 0; r < 2; r++) {
            int i = tid + r * 256;
            int kk = i >> 6, m = i & 63;
            As[kk][m] = fea[((size_t)b * CC + (k0 + kk)) * TT + t0 + m];
            Bs[kk][m] = i2h_w[(k0 + kk) * HH + h0 + m];
        }
        __syncthreads();
        #pragma unroll
        for (int kk = 0; kk < 8; kk++) {
            float a[4], bv[4];
            #pragma unroll
            for (int i = 0; i < 4; i++) a[i] = As[kk][ty * 4 + i];
            #pragma unroll
            for (int j = 0; j < 4; j++) bv[j] = Bs[kk][tx * 4 + j];
            #pragma unroll
            for (int i = 0; i < 4; i++)
                #pragma unroll
                for (int j = 0; j < 4; j++) acc[i][j] += a[i] * bv[j];
        }
        __syncthreads();
    }
    #pragma unroll
    for (int i = 0; i < 4; i++) {
        size_t base = ((size_t)b * TT + t0 + ty * 4 + i) * HH + h0 + tx * 4;
        *(__half2*)&d_proj_h[base]     = __floats2half2_rn(acc[i][0], acc[i][1]);
        *(__half2*)&d_proj_h[base + 2] = __floats2half2_rn(acc[i][2], acc[i][3]);
    }
}

// ---------------- decode: 2 CTAs per batch (T-split + col-split) ----------------
__global__ __launch_bounds__(1024, 1) void k_decode(
    const int* __restrict__ targets,
    const float* __restrict__ score_w,
    const float* __restrict__ b_ih, const float* __restrict__ b_hh,
    const float* __restrict__ sg1_b, const float* __restrict__ sg2_w,
    const float* __restrict__ sg2_b, const float* __restrict__ lg1_b,
    const float* __restrict__ lg2_w, const float* __restrict__ lg2_b,
    const float* __restrict__ h2h_b,
    float* __restrict__ out)
{
    __shared__ __align__(16) float s_w[HT];       // e -> unnormalized exp weights
    __shared__ __align__(16) float s_ctx[CC];     // partial ctx -> combined ctx
    __shared__ __align__(16) float s_hid[HH];
    __shared__ __align__(16) float s_ph[HH];
    __shared__ __align__(16) float s_g[NG];
    __shared__ __align__(16) float s_scr[4096];   // 16 KB partials (gemm / heads)
    __shared__ __align__(16) float s_s1[HH];
    __shared__ float s_red[16];
    __shared__ float s_mS[2];

    int b = blockIdx.x >> 1, p = blockIdx.x & 1, q = 1 - p;
    int tid = threadIdx.x, wid = tid >> 5, lane = tid & 31;
    const __half* w_g1  = d_hw_h + (size_t)p * HH * HH;       // sg1 (p=0) / lg1 (p=1)
    const __half* w_h2h = d_hw_h + (size_t)2 * HH * HH;
    const float*  b_g1  = p ? lg1_b : sg1_b;

    if (tid < HH) { s_hid[tid] = 0.f; s_ph[tid] = h2h_b[tid]; }   // h0=0 -> ph=bias
    float rsw[8];
    #pragma unroll
    for (int i = 0; i < 8; i++) rsw[i] = score_w[lane * 8 + i];
    __syncthreads();

    for (int s = 0; s < STEPS; s++) {
        int ch = targets[b * STEPS + s];
        int par = s & 1;
        float rph[8];
        #pragma unroll
        for (int i = 0; i < 8; i++) rph[i] = s_ph[lane * 8 + i];

        // ---- scores for t in [p*HT, p*HT+HT): warp wid covers 16 t ----
        const uint4* pbase =
            (const uint4*)&d_proj_h[((size_t)b * TT + p * HT + wid * 16) * HH + lane * 8];
        #pragma unroll 4
        for (int tt = 0; tt < 16; tt++) {
            uint4 pv = pbase[(size_t)tt * (HH / 8)];
            float pf[8]; h8_to_f(pv, pf);
            float a = tanha(pf[0] + rph[0]) * rsw[0] + tanha(pf[1] + rph[1]) * rsw[1]
                    + tanha(pf[2] + rph[2]) * rsw[2] + tanha(pf[3] + rph[3]) * rsw[3]
                    + tanha(pf[4] + rph[4]) * rsw[4] + tanha(pf[5] + rph[5]) * rsw[5]
                    + tanha(pf[6] + rph[6]) * rsw[6] + tanha(pf[7] + rph[7]) * rsw[7];
            #pragma unroll
            for (int o = 16; o; o >>= 1) a += __shfl_xor_sync(~0u, a, o);
            if (lane == 0) s_w[wid * 16 + tt] = a;
        }
        __syncthreads();

        // ---- local softmax stats over this half (512 elems, 16 warps) ----
        if (tid < HT) {
            float e = s_w[tid];
            float m = e;
            #pragma unroll
            for (int o = 16; o; o >>= 1) m = fmaxf(m, __shfl_xor_sync(~0u, m, o));
            if (lane == 0) s_red[wid] = m;
        }
        __syncthreads();
        if (tid < HT) {
            float m = s_red[0];
            #pragma unroll
            for (int i = 1; i < 16; i++) m = fmaxf(m, s_red[i]);
            float ex = __expf(s_w[tid] - m);
            s_w[tid] = ex;                       // unnormalized weights
            float sm = ex;
            #pragma unroll
            for (int o = 16; o; o >>= 1) sm += __shfl_xor_sync(~0u, sm, o);
            __syncthreads();
            if (lane == 0) s_red[wid] = sm;
            if (tid == 0) s_mS[0] = m;
        } else __syncthreads();
        __syncthreads();
        if (tid == 0) {
            float sm = 0.f;
            #pragma unroll
            for (int i = 0; i < 16; i++) sm += s_red[i];
            s_mS[1] = sm;
        }
        __syncthreads();

        // ---- partial ctx: v[c] = sum_{t half} w[t] * fea[b,c,p*HT+t], all 512 c ----
        #pragma unroll 1
        for (int cc = 0; cc < 16; cc++) {
            int c = wid * 16 + cc;
            const __half* f = &d_fea_h[((size_t)b * CC + c) * TT + p * HT];
            float acc = 0.f;
            #pragma unroll
            for (int qq = 0; qq < 2; qq++) {
                int t = qq * 256 + lane * 8;
                uint4 fv = *(const uint4*)&f[t];
                float fw[8]; h8_to_f(fv, fw);
                const float4* av = (const float4*)&s_w[t];
                float4 a0 = av[0], a1 = av[1];
                acc += fw[0]*a0.x + fw[1]*a0.y + fw[2]*a0.z + fw[3]*a0.w
                     + fw[4]*a1.x + fw[5]*a1.y + fw[6]*a1.z + fw[7]*a1.w;
            }
            #pragma unroll
            for (int o = 16; o; o >>= 1) acc += __shfl_xor_sync(~0u, acc, o);
            if (lane == 0) s_ctx[c] = acc;
        }
        __syncthreads();

        // ---- exchange 1: (v, m, S) ----
        {
            float* buf = &d_xv[par][b][p][0];
            if (tid < HT) buf[tid] = s_ctx[tid];
            if (tid == 0) { buf[512] = s_mS[0]; buf[513] = s_mS[1]; }
            __syncthreads();
            if (tid == 0) {
                __threadfence();
                atomicExch(&d_flag[b][p][0], s + 1);
                while (atomicAdd(&d_flag[b][q][0], 0) < s + 1) {}
                __threadfence();
            }
            __syncthreads();
            const float* pb = &d_xv[par][b][q][0];
            float mpeer = pb[512], Speer = pb[513];
            float mloc = s_mS[0], Sloc = s_mS[1];
            float m0 = p ? mpeer : mloc, S0 = p ? Speer : Sloc;
            float m1 = p ? mloc : mpeer, S1 = p ? Sloc : Speer;
            float M  = fmaxf(m0, m1);
            float f0 = __expf(m0 - M), f1 = __expf(m1 - M);
            float inv = 1.f / (S0 * f0 + S1 * f1);
            float w0 = f0 * inv, w1 = f1 * inv;
            if (tid < HT) {
                float vpeer = pb[tid];
                float v0 = p ? vpeer : s_ctx[tid];
                float v1 = p ? s_ctx[tid] : vpeer;
                s_ctx[tid] = v0 * w0 + v1 * w1;   // identical in both CTAs
            }
        }
        __syncthreads();

        // ---- GRU gemm half: g[n] for n in [p*512, p*512+512), k-split x8 ----
        {
            int kq = tid >> 7, ng = tid & 127, n = p * 512 + ng * 4;
            float acc[4] = {};
            int k0 = kq * 96;
            #pragma unroll 4
            for (int k = k0; k < k0 + 96; k++) {
                int row  = (k < 512) ? k : k + 30;          // skip onehot rows
                float uv = (k < 512) ? s_ctx[k] : s_hid[k - 512];
                uint2 wv = *(const uint2*)&d_wcat_h[(size_t)row * NG + n];
                float w[4]; h4_to_f(wv, w);
                #pragma unroll
                for (int j = 0; j < 4; j++) acc[j] += uv * w[j];
            }
            *(float4*)&s_scr[kq * 512 + ng * 4] = make_float4(acc[0], acc[1], acc[2], acc[3]);
        }
        __syncthreads();
        if (tid < 512) {
            float g = __half2float(d_wcat_h[(size_t)(512 + ch) * NG + p * 512 + tid]);
            #pragma unroll
            for (int kq = 0; kq < 8; kq++) g += s_scr[kq * 512 + tid];
            s_g[p * 512 + tid] = g;
            d_xg[par][b][p][tid] = g;
        }
        __syncthreads();

        // ---- exchange 2: g halves ----
        if (tid == 0) {
            __threadfence();
            atomicExch(&d_flag[b][p][1], s + 1);
            while (atomicAdd(&d_flag[b][q][1], 0) < s + 1) {}
            __threadfence();
        }
        __syncthreads();
        if (tid < 512) s_g[q * 512 + tid] = d_xg[par][b][q][tid];
        __syncthreads();

        // ---- gates (redundant in both CTAs -> identical s_hid) ----
        if (tid < HH) {
            int h = tid;
            float gr  = s_g[h]       + b_ih[h]       + b_hh[h];
            float gz  = s_g[256 + h] + b_ih[256 + h] + b_hh[256 + h];
            float ghn = s_g[768 + h] + b_hh[512 + h];
            float gxn = (s_g[512 + h] - s_g[768 + h]) + b_ih[512 + h];
            float r = 1.f / (1.f + expf(-gr));
            float z = 1.f / (1.f + expf(-gz));
            float n = tanhf(gxn + r * ghn);
            s_hid[h] = (1.f - z) * n + z * s_hid[h];
        }
        __syncthreads();

        // ---- heads: this CTA does (sg1|lg1) matvec + h2h matvec, k-split x8 ----
        {
            int mm = tid >> 9, idx = tid & 511, kq = idx >> 6, hg = idx & 63;
            const __half* w = (mm == 0) ? w_g1 : w_h2h;
            float a[4] = {};
            int k0 = kq * 32;
            #pragma unroll 4
            for (int k = k0; k < k0 + 32; k++) {
                float hv = s_hid[k];
                uint2 wv = *(const uint2*)&w[k * HH + hg * 4];
                float wf[4]; h4_to_f(wv, wf);
                #pragma unroll
                for (int j = 0; j < 4; j++) a[j] += hv * wf[j];
            }
            *(float4*)&s_scr[mm * 2048 + kq * 256 + hg * 4] = make_float4(a[0], a[1], a[2], a[3]);
        }
        __syncthreads();
        if (tid < 512) {
            int mm = tid >> 8, h = tid & 255;
            float v = 0.f;
            #pragma unroll
            for (int kq = 0; kq < 8; kq++) v += s_scr[mm * 2048 + kq * 256 + h];
            if (mm == 0) s_s1[h] = v + b_g1[h];
            else         s_ph[h] = v + h2h_b[h];    // redundant in both CTAs
        }
        __syncthreads();

        // ---- output heads ----
        if (p == 0) {
            if (tid < NE) {
                float sv = sg2_b[tid];
                #pragma unroll 8
                for (int k = 0; k < HH; k++) sv += s_s1[k] * sg2_w[k * NE + tid];
                out[((size_t)b * STEPS + s) * NE + tid] = sv;
            }
        } else {
            if (tid < 4) {
                float lv = lg2_b[tid];
                #pragma unroll 8
                for (int k = 0; k < HH; k++) lv += s_s1[k] * lg2_w[k * 4 + tid];
                out[(size_t)BB * STEPS * NE + ((size_t)b * STEPS + s) * 4 + tid] =
                    1.f / (1.f + expf(-lv));
            }
        }
        __syncthreads();
    }
}

// ---------------- launch (decode is global launch #5 incl. 2 harness prelaunches) ----
extern "C" void kernel_launch(void* const* d_in, const int* in_sizes, int n_in,
                              void* d_out, int out_size) {
    const float* fea      = (const float*)d_in[0];
    const int*   targets  = (const int*)  d_in[1];
    const float* i2h_w    = (const float*)d_in[2];
    const float* h2h_w    = (const float*)d_in[3];
    const float* h2h_b    = (const float*)d_in[4];
    const float* score_w  = (const float*)d_in[5];
    const float* gru_w_ih = (const float*)d_in[6];
    const float* gru_w_hh = (const float*)d_in[7];
    const float* gru_b_ih = (const float*)d_in[8];
    const float* gru_b_hh = (const float*)d_in[9];
    const float* sg1_w    = (const float*)d_in[10];
    const float* sg1_b    = (const float*)d_in[11];
    const float* sg2_w    = (const float*)d_in[12];
    const float* sg2_b    = (const float*)d_in[13];
    const float* lg1_w    = (const float*)d_in[14];
    const float* lg1_b    = (const float*)d_in[15];
    const float* lg2_w    = (const float*)d_in[16];
    const float* lg2_b    = (const float*)d_in[17];
    float* out = (float*)d_out;

    int setup_elems = WROWS * NG + 3 * HH * HH;
    k_setup<<<(setup_elems + 255) / 256, 256>>>(gru_w_ih, gru_w_hh, sg1_w, lg1_w, h2h_w);
    k_conv<<<(int)(((size_t)BB * CC * TT / 4 + 255) / 256), 256>>>(fea);
    k_proj<<<dim3(TT / 64, HH / 64, BB), 256>>>(fea, i2h_w);
    k_decode<<<BB * 2, 1024>>>(targets, score_w,
                               gru_b_ih, gru_b_hh,
                               sg1_b, sg2_w, sg2_b,
                               lg1_b, lg2_w, lg2_b,
                               h2h_b, out);
}